// round 2
// baseline (speedup 1.0000x reference)
#include <cuda_runtime.h>
#include <cuda_bf16.h>
#include <math_constants.h>

// Problem constants (fixed by the reference)
constexpr int B_  = 128;
constexpr int T_  = 256;
constexpr int C_  = 384;
constexpr int H_  = 6;
constexpr int D_  = 64;
constexpr int FF_ = 1536;
constexpr int M_  = B_ * T_;   // 32768 rows

// ---------------- scratch (static device allocations; allowed) ----------------
__device__ float g_h  [M_ * C_];   // LN output (reused for ln1 and ln2)
__device__ float g_k  [M_ * C_];   // K  (B,H,T,D)
__device__ float g_q  [M_ * C_];   // Q  (B,H,T,D)
__device__ float g_v  [M_ * C_];   // V  (B,H,T,D)
__device__ float g_att[M_ * C_];   // attention out, (B,T,C)
__device__ float g_x1 [M_ * C_];   // x + attn proj  (B,T,C)
__device__ float g_mid[M_ * FF_];  // FFN hidden

// ---------------- LayerNorm: one block (128 thr) per row of 384 ----------------
__global__ void ln_kernel(const float* __restrict__ x, const float* __restrict__ g,
                          const float* __restrict__ b, float* __restrict__ out)
{
    int row = blockIdx.x;
    const float* xr = x + row * C_;
    int tid = threadIdx.x;            // 128 threads
    float v0 = xr[tid], v1 = xr[tid + 128], v2 = xr[tid + 256];
    float s  = v0 + v1 + v2;
    float sq = v0 * v0 + v1 * v1 + v2 * v2;
    #pragma unroll
    for (int o = 16; o; o >>= 1) {
        s  += __shfl_xor_sync(0xffffffffu, s,  o);
        sq += __shfl_xor_sync(0xffffffffu, sq, o);
    }
    __shared__ float red[2][4];
    int wid = tid >> 5, lane = tid & 31;
    if (lane == 0) { red[0][wid] = s; red[1][wid] = sq; }
    __syncthreads();
    s  = red[0][0] + red[0][1] + red[0][2] + red[0][3];
    sq = red[1][0] + red[1][1] + red[1][2] + red[1][3];
    float mu  = s * (1.0f / C_);
    float var = sq * (1.0f / C_) - mu * mu;
    float inv = rsqrtf(var + 1e-5f);
    float* orow = out + row * C_;
    orow[tid]       = (v0 - mu) * inv * g[tid]       + b[tid];
    orow[tid + 128] = (v1 - mu) * inv * g[tid + 128] + b[tid + 128];
    orow[tid + 256] = (v2 - mu) * inv * g[tid + 256] + b[tid + 256];
}

// ---------------- Tiled SGEMM: 128x64 tile, BK=16, 256 threads, 8x4/thread ----
// FLAGS bits: 1=HEADB (B is (H,C,D) head-blocked), 2=BHTD dest, 4=RELU, 8=RESID
template<int FLAGS>
__global__ void __launch_bounds__(256)
gemm_k(const float* __restrict__ A, const float* __restrict__ Bm,
       const float* __restrict__ bias, const float* __restrict__ resid,
       float* __restrict__ Cout, int K, int N, int ldb)
{
    constexpr bool HEADB = (FLAGS & 1) != 0;
    constexpr bool BHTD  = (FLAGS & 2) != 0;
    constexpr bool RELU  = (FLAGS & 4) != 0;
    constexpr bool RESID = (FLAGS & 8) != 0;

    __shared__ float As[16][132];   // transposed A tile [k][m], padded
    __shared__ float Bs[16][64];    // B tile [k][n]

    int m0 = blockIdx.x * 128;
    int n0 = blockIdx.y * 64;

    const float* Bp;
    int ldbe;
    if (HEADB) { Bp = Bm + (n0 >> 6) * K * 64; ldbe = 64; }
    else       { Bp = Bm + n0;                 ldbe = ldb; }

    int tid = threadIdx.x;
    int ty = tid >> 4;       // 0..15  -> m group of 8
    int tx = tid & 15;       // 0..15  -> n group of 4

    int arow0 = tid >> 2;    // 0..63
    int ac4   = tid & 3;     // 0..3

    float acc[8][4];
    #pragma unroll
    for (int i = 0; i < 8; i++)
        #pragma unroll
        for (int j = 0; j < 4; j++) acc[i][j] = 0.0f;

    for (int k0 = 0; k0 < K; k0 += 16) {
        // A tile (128x16) -> transposed smem
        #pragma unroll
        for (int u = 0; u < 2; u++) {
            int row = arow0 + u * 64;
            float4 av = *(const float4*)(A + (long long)(m0 + row) * K + k0 + ac4 * 4);
            As[ac4 * 4 + 0][row] = av.x;
            As[ac4 * 4 + 1][row] = av.y;
            As[ac4 * 4 + 2][row] = av.z;
            As[ac4 * 4 + 3][row] = av.w;
        }
        // B tile (16x64)
        {
            float4 bv = *(const float4*)(Bp + (long long)(k0 + ty) * ldbe + tx * 4);
            *(float4*)&Bs[ty][tx * 4] = bv;
        }
        __syncthreads();
        #pragma unroll
        for (int k = 0; k < 16; k++) {
            float a[8], bb[4];
            #pragma unroll
            for (int i = 0; i < 8; i++) a[i] = As[k][ty * 8 + i];
            #pragma unroll
            for (int j = 0; j < 4; j++) bb[j] = Bs[k][tx * 4 + j];
            #pragma unroll
            for (int i = 0; i < 8; i++)
                #pragma unroll
                for (int j = 0; j < 4; j++)
                    acc[i][j] += a[i] * bb[j];
        }
        __syncthreads();
    }

    // epilogue
    #pragma unroll
    for (int i = 0; i < 8; i++) {
        int m = m0 + ty * 8 + i;
        #pragma unroll
        for (int j = 0; j < 4; j++) {
            int n = n0 + tx * 4 + j;
            float v = acc[i][j] + bias[n];
            if (RELU)  v = fmaxf(v, 0.0f);
            if (RESID) v += resid[(long long)m * N + n];
            if (BHTD) {
                int bb_ = m >> 8;      // m / T_
                int t   = m & 255;     // m % T_
                int hh  = n >> 6;      // n / 64
                int d   = n & 63;
                Cout[(((long long)(bb_ * H_ + hh) << 8) + t) * 64 + d] = v;
            } else {
                Cout[(long long)m * N + n] = v;
            }
        }
    }
}

// ---------------- Attention: one CTA per (t_tile=64 rows, head, batch) --------
// scores[t,s] = K[t]·Q[s] * C^-0.5 (reference quirk), causal s<=t, softmax over s,
// out = P @ V, written to (B,T,C) with head-concat.
constexpr int ATTN_SMEM = (2 * 64 * 68 + 64 * 257) * 4;   // ~98.25 KB

__global__ void __launch_bounds__(256)
attn_kernel(const float* __restrict__ Kg, const float* __restrict__ Qg,
            const float* __restrict__ Vg, float* __restrict__ Og)
{
    extern __shared__ float sm[];
    float* Ks = sm;                  // [64][68]
    float* Qs = sm + 64 * 68;        // [64][68] (reused for V tiles)
    float* P  = sm + 2 * 64 * 68;    // [64][257]

    int tt = blockIdx.x;             // t-tile 0..3
    int h  = blockIdx.y;
    int b  = blockIdx.z;
    int bh = b * H_ + h;
    const float* Kb = Kg + (long long)bh * T_ * D_;
    const float* Qb = Qg + (long long)bh * T_ * D_;
    const float* Vb = Vg + (long long)bh * T_ * D_;

    int tid = threadIdx.x;
    int ty = tid >> 4, tx = tid & 15;

    // load K tile for our 64 t-rows
    for (int qd = tid; qd < 64 * 16; qd += 256) {
        int r = qd >> 4, c4 = qd & 15;
        float4 v = *(const float4*)(Kb + (tt * 64 + r) * 64 + c4 * 4);
        *(float4*)&Ks[r * 68 + c4 * 4] = v;
    }

    const float scale = rsqrtf((float)C_);
    int nst = tt + 1;                // causal: only s-tiles <= t-tile

    // Phase 1: scores into P (with mask+scale)
    for (int st = 0; st < nst; st++) {
        __syncthreads();
        for (int qd = tid; qd < 64 * 16; qd += 256) {
            int r = qd >> 4, c4 = qd & 15;
            *(float4*)&Qs[r * 68 + c4 * 4] =
                *(const float4*)(Qb + (st * 64 + r) * 64 + c4 * 4);
        }
        __syncthreads();
        float acc[4][4];
        #pragma unroll
        for (int i = 0; i < 4; i++)
            #pragma unroll
            for (int j = 0; j < 4; j++) acc[i][j] = 0.0f;
        #pragma unroll
        for (int d = 0; d < 64; d++) {
            float a[4], bb[4];
            #pragma unroll
            for (int i = 0; i < 4; i++) a[i] = Ks[(ty * 4 + i) * 68 + d];
            #pragma unroll
            for (int j = 0; j < 4; j++) bb[j] = Qs[(tx * 4 + j) * 68 + d];
            #pragma unroll
            for (int i = 0; i < 4; i++)
                #pragma unroll
                for (int j = 0; j < 4; j++)
                    acc[i][j] += a[i] * bb[j];
        }
        #pragma unroll
        for (int i = 0; i < 4; i++) {
            int tg = tt * 64 + ty * 4 + i;
            #pragma unroll
            for (int j = 0; j < 4; j++) {
                int sg = st * 64 + tx * 4 + j;
                P[(ty * 4 + i) * 257 + st * 64 + tx * 4 + j] =
                    (sg <= tg) ? acc[i][j] * scale : -CUDART_INF_F;
            }
        }
    }
    __syncthreads();

    // Phase 2: row softmax (8 warps x 8 rows)
    int wid = tid >> 5, lane = tid & 31;
    int send = nst * 64;
    for (int r = wid; r < 64; r += 8) {
        float* Pr = P + r * 257;
        float mx = -CUDART_INF_F;
        for (int s = lane; s < send; s += 32) mx = fmaxf(mx, Pr[s]);
        #pragma unroll
        for (int o = 16; o; o >>= 1) mx = fmaxf(mx, __shfl_xor_sync(0xffffffffu, mx, o));
        float sum = 0.0f;
        for (int s = lane; s < send; s += 32) {
            float e = __expf(Pr[s] - mx);
            Pr[s] = e;
            sum += e;
        }
        #pragma unroll
        for (int o = 16; o; o >>= 1) sum += __shfl_xor_sync(0xffffffffu, sum, o);
        float inv = 1.0f / sum;
        for (int s = lane; s < send; s += 32) Pr[s] *= inv;
    }

    // Phase 3: out = P @ V
    float oacc[4][4];
    #pragma unroll
    for (int i = 0; i < 4; i++)
        #pragma unroll
        for (int j = 0; j < 4; j++) oacc[i][j] = 0.0f;

    for (int st = 0; st < nst; st++) {
        __syncthreads();
        for (int qd = tid; qd < 64 * 16; qd += 256) {
            int r = qd >> 4, c4 = qd & 15;
            *(float4*)&Qs[r * 68 + c4 * 4] =
                *(const float4*)(Vb + (st * 64 + r) * 64 + c4 * 4);
        }
        __syncthreads();
        for (int s = 0; s < 64; s++) {
            float a[4], bb[4];
            #pragma unroll
            for (int i = 0; i < 4; i++) a[i] = P[(ty * 4 + i) * 257 + st * 64 + s];
            #pragma unroll
            for (int j = 0; j < 4; j++) bb[j] = Qs[s * 68 + tx * 4 + j];
            #pragma unroll
            for (int i = 0; i < 4; i++)
                #pragma unroll
                for (int j = 0; j < 4; j++)
                    oacc[i][j] += a[i] * bb[j];
        }
    }

    // write to (B,T,C): col = h*64 + d
    #pragma unroll
    for (int i = 0; i < 4; i++) {
        int t = tt * 64 + ty * 4 + i;
        #pragma unroll
        for (int j = 0; j < 4; j++) {
            int col = h * 64 + tx * 4 + j;
            Og[((long long)b * T_ + t) * C_ + col] = oacc[i][j];
        }
    }
}

// ---------------- host orchestration -------------------------------------------
extern "C" void kernel_launch(void* const* d_in, const int* in_sizes, int n_in,
                              void* d_out, int out_size)
{
    const float* x     = (const float*)d_in[0];
    const float* ln1_g = (const float*)d_in[1];
    const float* ln1_b = (const float*)d_in[2];
    const float* Wk    = (const float*)d_in[3];
    const float* bk    = (const float*)d_in[4];
    const float* Wq    = (const float*)d_in[5];
    const float* bq    = (const float*)d_in[6];
    const float* Wv    = (const float*)d_in[7];
    const float* bv    = (const float*)d_in[8];
    const float* Wp    = (const float*)d_in[9];
    const float* bp    = (const float*)d_in[10];
    const float* ln2_g = (const float*)d_in[11];
    const float* ln2_b = (const float*)d_in[12];
    const float* W1    = (const float*)d_in[13];
    const float* b1    = (const float*)d_in[14];
    const float* W2    = (const float*)d_in[15];
    const float* b2    = (const float*)d_in[16];
    float* out = (float*)d_out;

    float *h, *k, *q, *v, *att, *x1, *mid;
    cudaGetSymbolAddress((void**)&h,   g_h);
    cudaGetSymbolAddress((void**)&k,   g_k);
    cudaGetSymbolAddress((void**)&q,   g_q);
    cudaGetSymbolAddress((void**)&v,   g_v);
    cudaGetSymbolAddress((void**)&att, g_att);
    cudaGetSymbolAddress((void**)&x1,  g_x1);
    cudaGetSymbolAddress((void**)&mid, g_mid);

    cudaFuncSetAttribute(attn_kernel,
                         cudaFuncAttributeMaxDynamicSharedMemorySize, ATTN_SMEM);

    // 1. LN1
    ln_kernel<<<M_, 128>>>(x, ln1_g, ln1_b, h);

    // 2. QKV projections  (HEADB | BHTD)
    dim3 gq(M_ / 128, C_ / 64);
    gemm_k<1 | 2><<<gq, 256>>>(h, Wk, bk, nullptr, k, C_, C_, 64);
    gemm_k<1 | 2><<<gq, 256>>>(h, Wq, bq, nullptr, q, C_, C_, 64);
    gemm_k<1 | 2><<<gq, 256>>>(h, Wv, bv, nullptr, v, C_, C_, 64);

    // 3. attention
    attn_kernel<<<dim3(T_ / 64, H_, B_), 256, ATTN_SMEM>>>(k, q, v, att);

    // 4. output projection + residual  (RESID)
    gemm_k<8><<<dim3(M_ / 128, C_ / 64), 256>>>(att, Wp, bp, x, x1, C_, C_, C_);

    // 5. LN2
    ln_kernel<<<M_, 128>>>(x1, ln2_g, ln2_b, h);

    // 6. FFN up + relu  (RELU)
    gemm_k<4><<<dim3(M_ / 128, FF_ / 64), 256>>>(h, W1, b1, nullptr, mid, C_, FF_, FF_);

    // 7. FFN down + residual -> d_out  (RESID)
    gemm_k<8><<<dim3(M_ / 128, C_ / 64), 256>>>(mid, W2, b2, x1, out, FF_, C_, C_);
}

// round 4
// speedup vs baseline: 2.7656x; 2.7656x over previous
#include <cuda_runtime.h>
#include <cuda_bf16.h>
#include <math_constants.h>
#include <cstdint>
#include <cstddef>

// Problem constants
constexpr int B_  = 128;
constexpr int T_  = 256;
constexpr int C_  = 384;
constexpr int H_  = 6;
constexpr int D_  = 64;
constexpr int FF_ = 1536;
constexpr int M_  = B_ * T_;     // 32768
constexpr int KC1 = 3 * C_;      // 1152
constexpr int KC2 = 3 * FF_;     // 4608

// ---------------- scratch ----------------
__device__ __nv_bfloat16 g_acatA[(size_t)M_ * KC1];
__device__ __nv_bfloat16 g_acat4[(size_t)M_ * KC2];
__device__ __nv_bfloat16 g_bqkv [(size_t)(3 * C_) * KC1];
__device__ __nv_bfloat16 g_bcp  [(size_t)C_  * KC1];
__device__ __nv_bfloat16 g_bc1  [(size_t)FF_ * KC1];
__device__ __nv_bfloat16 g_bc2  [(size_t)C_  * KC2];
__device__ float g_biasqkv[3 * C_];
__device__ float g_k  [M_ * C_];
__device__ float g_q  [M_ * C_];
__device__ float g_v  [M_ * C_];
__device__ float g_att[M_ * C_];
__device__ float g_x1 [M_ * C_];

// ---------------- helpers ----------------
__device__ __forceinline__ uint32_t smem_u32(const void* p) {
    uint32_t a;
    asm("{ .reg .u64 t; cvta.to.shared.u64 t, %1; cvt.u32.u64 %0, t; }" : "=r"(a) : "l"(p));
    return a;
}
__device__ __forceinline__ void cp16(uint32_t dst, const void* src) {
    asm volatile("cp.async.cg.shared.global [%0], [%1], 16;" :: "r"(dst), "l"(src));
}
#define CP_COMMIT() asm volatile("cp.async.commit_group;" ::: "memory")
#define CP_WAIT0()  asm volatile("cp.async.wait_group 0;"  ::: "memory")
#define CP_WAIT1()  asm volatile("cp.async.wait_group 1;"  ::: "memory")

__device__ __forceinline__ void ldm_x4(uint32_t* r, uint32_t addr) {
    asm volatile("ldmatrix.sync.aligned.m8n8.x4.shared.b16 {%0,%1,%2,%3}, [%4];"
        : "=r"(r[0]), "=r"(r[1]), "=r"(r[2]), "=r"(r[3]) : "r"(addr));
}
__device__ __forceinline__ void mma16816(float* c, const uint32_t* a, uint32_t b0, uint32_t b1) {
    asm volatile("mma.sync.aligned.m16n8k16.row.col.f32.bf16.bf16.f32 "
        "{%0,%1,%2,%3}, {%4,%5,%6,%7}, {%8,%9}, {%0,%1,%2,%3};"
        : "+f"(c[0]), "+f"(c[1]), "+f"(c[2]), "+f"(c[3])
        : "r"(a[0]), "r"(a[1]), "r"(a[2]), "r"(a[3]), "r"(b0), "r"(b1));
}
__device__ __forceinline__ void split2(float v, __nv_bfloat16& hi, __nv_bfloat16& lo) {
    hi = __float2bfloat16(v);
    lo = __float2bfloat16(v - __bfloat162float(hi));
}
__device__ __forceinline__ uint32_t packbf(float a, float b) {
    __nv_bfloat162 p(__float2bfloat16(a), __float2bfloat16(b));
    return *(uint32_t*)&p;
}

// ---------------- LayerNorm -> split activation cat [hi|lo|hi] ----------------
__global__ void ln_split_kernel(const float* __restrict__ x, const float* __restrict__ g,
                                const float* __restrict__ b, __nv_bfloat16* __restrict__ acat)
{
    int row = blockIdx.x;
    const float* xr = x + (size_t)row * C_;
    int tid = threadIdx.x;
    float v0 = xr[tid], v1 = xr[tid + 128], v2 = xr[tid + 256];
    float s  = v0 + v1 + v2;
    float sq = v0 * v0 + v1 * v1 + v2 * v2;
    #pragma unroll
    for (int o = 16; o; o >>= 1) {
        s  += __shfl_xor_sync(0xffffffffu, s,  o);
        sq += __shfl_xor_sync(0xffffffffu, sq, o);
    }
    __shared__ float red[2][4];
    int wid = tid >> 5, lane = tid & 31;
    if (lane == 0) { red[0][wid] = s; red[1][wid] = sq; }
    __syncthreads();
    s  = red[0][0] + red[0][1] + red[0][2] + red[0][3];
    sq = red[1][0] + red[1][1] + red[1][2] + red[1][3];
    float mu  = s * (1.0f / C_);
    float var = sq * (1.0f / C_) - mu * mu;
    float inv = rsqrtf(var + 1e-5f);
    __nv_bfloat16* orow = acat + (size_t)row * KC1;
    #pragma unroll
    for (int u = 0; u < 3; u++) {
        int k = tid + u * 128;
        float vv = (u == 0 ? v0 : (u == 1 ? v1 : v2));
        float y = (vv - mu) * inv * g[k] + b[k];
        __nv_bfloat16 hi, lo; split2(y, hi, lo);
        orow[k] = hi; orow[C_ + k] = lo; orow[2 * C_ + k] = hi;
    }
}

// ---------------- fp32 rows -> split activation cat --------------------------
__global__ void split_rows_kernel(const float* __restrict__ in, __nv_bfloat16* __restrict__ acat)
{
    size_t idx = (size_t)blockIdx.x * 256 + threadIdx.x;
    int m = (int)(idx / C_);
    int k = (int)(idx % C_);
    float v = in[idx];
    __nv_bfloat16 hi, lo; split2(v, hi, lo);
    __nv_bfloat16* orow = acat + (size_t)m * KC1;
    orow[k] = hi; orow[C_ + k] = lo; orow[2 * C_ + k] = hi;
}

// ---------------- weight builders: Bcat[n][k'] = [hi|hi|lo] ------------------
__global__ void build_bcat_kernel(const float* __restrict__ W, __nv_bfloat16* __restrict__ Bcat,
                                  int K, int N)
{
    size_t idx = (size_t)blockIdx.x * 256 + threadIdx.x;
    if (idx >= (size_t)K * N) return;
    int n = (int)(idx / K);
    int k = (int)(idx % K);
    float v = W[(size_t)k * N + n];
    __nv_bfloat16 hi, lo; split2(v, hi, lo);
    size_t base = (size_t)n * 3 * K;
    Bcat[base + k] = hi; Bcat[base + K + k] = hi; Bcat[base + 2 * K + k] = lo;
}

__global__ void build_bcat_qkv_kernel(const float* __restrict__ Wk, const float* __restrict__ Wq,
                                      const float* __restrict__ Wv, __nv_bfloat16* __restrict__ Bcat)
{
    size_t idx = (size_t)blockIdx.x * 256 + threadIdx.x;
    if (idx >= (size_t)(3 * C_) * C_) return;
    int n = (int)(idx / C_);
    int k = (int)(idx % C_);
    int sel = n / C_;
    int nn = n - sel * C_;
    int h = nn >> 6, d = nn & 63;
    const float* Ws = (sel == 0) ? Wk : (sel == 1) ? Wq : Wv;
    float v = Ws[((size_t)h * C_ + k) * 64 + d];
    __nv_bfloat16 hi, lo; split2(v, hi, lo);
    size_t base = (size_t)n * KC1;
    Bcat[base + k] = hi; Bcat[base + C_ + k] = hi; Bcat[base + 2 * C_ + k] = lo;
}

__global__ void bias_concat_kernel(const float* __restrict__ bk, const float* __restrict__ bq,
                                   const float* __restrict__ bv, float* __restrict__ out)
{
    int t = blockIdx.x * 256 + threadIdx.x;
    if (t >= 3 * C_) return;
    int sel = t / C_, nn = t % C_;
    out[t] = (sel == 0 ? bk : sel == 1 ? bq : bv)[nn];
}

// ---------------- mma.sync GEMM: 128x128 tile, BK=32, 8 warps -----------------
// FLAGS: 1 = QKV split store, 2 = ReLU + write split acat4, 4 = residual add, 0 = plain
template<int FLAGS>
__global__ void __launch_bounds__(256)
mma_gemm(const __nv_bfloat16* __restrict__ A, const __nv_bfloat16* __restrict__ Bc,
         const float* __restrict__ bias, const float* __restrict__ resid,
         float* __restrict__ out0, float* __restrict__ out1, float* __restrict__ out2,
         __nv_bfloat16* __restrict__ acat_out, int Kc, int N)
{
    __shared__ __align__(16) __nv_bfloat16 sA[2][128][40];
    __shared__ __align__(16) __nv_bfloat16 sB[2][128][40];

    int tid  = threadIdx.x;
    int wid  = tid >> 5;
    int lane = tid & 31;
    int wm = wid >> 2;          // 0..1 -> m offset *64
    int wn = wid & 3;           // 0..3 -> n offset *32
    int m0 = blockIdx.y * 128;
    int n0 = blockIdx.x * 128;
    int NC = Kc / 32;

    // loaders: thread -> (row = tid>>2 in 0..63, seg = tid&3); two row-halves each
    int lrow = tid >> 2;
    int lseg = tid & 3;
    const __nv_bfloat16* aRow0 = A  + (size_t)(m0 + lrow)      * Kc + lseg * 8;
    const __nv_bfloat16* aRow1 = A  + (size_t)(m0 + lrow + 64) * Kc + lseg * 8;
    const __nv_bfloat16* bRow0 = Bc + (size_t)(n0 + lrow)      * Kc + lseg * 8;
    const __nv_bfloat16* bRow1 = Bc + (size_t)(n0 + lrow + 64) * Kc + lseg * 8;

    uint32_t dA0 = smem_u32(&sA[0][lrow][lseg * 8]);
    uint32_t dA1 = smem_u32(&sA[0][lrow + 64][lseg * 8]);
    uint32_t dB0 = smem_u32(&sB[0][lrow][lseg * 8]);
    uint32_t dB1 = smem_u32(&sB[0][lrow + 64][lseg * 8]);
    constexpr uint32_t STG_A = sizeof(sA) / 2;   // bytes per stage
    constexpr uint32_t STG_B = sizeof(sB) / 2;

    auto load_chunk = [&](int c, int st) {
        size_t ko = (size_t)c * 32;
        uint32_t oa = st * STG_A, ob = st * STG_B;
        cp16(dA0 + oa, aRow0 + ko);
        cp16(dA1 + oa, aRow1 + ko);
        cp16(dB0 + ob, bRow0 + ko);
        cp16(dB1 + ob, bRow1 + ko);
    };

    // ldmatrix lane addressing
    int q = lane >> 3, i = lane & 7;
    // A x4: matrices (row+0,k0) (row+8,k0) (row+0,k0+8) (row+8,k0+8)
    uint32_t aAddr = smem_u32(&sA[0][wm * 64 + (q & 1) * 8 + i][(q >> 1) * 8]);
    // B x4: matrices (ntA,k0) (ntA,k0+8) (ntB,k0) (ntB,k0+8); ntA=pair*16, ntB=pair*16+8
    uint32_t bAddr = smem_u32(&sB[0][wn * 32 + (q >> 1) * 8 + i][(q & 1) * 8]);

    float acc[4][4][4];
    #pragma unroll
    for (int mt = 0; mt < 4; mt++)
        #pragma unroll
        for (int nt = 0; nt < 4; nt++)
            #pragma unroll
            for (int r = 0; r < 4; r++) acc[mt][nt][r] = 0.0f;

    load_chunk(0, 0); CP_COMMIT();
    if (NC > 1) { load_chunk(1, 1); CP_COMMIT(); }

    for (int c = 0; c < NC; c++) {
        int st = c & 1;
        if (c + 1 < NC) CP_WAIT1(); else CP_WAIT0();
        __syncthreads();

        uint32_t aS = aAddr + st * STG_A;
        uint32_t bS = bAddr + st * STG_B;
        #pragma unroll
        for (int ks = 0; ks < 2; ks++) {
            uint32_t af[4][4], bf[2][4];
            #pragma unroll
            for (int mt = 0; mt < 4; mt++)
                ldm_x4(af[mt], aS + mt * 16 * 80 + ks * 32);
            #pragma unroll
            for (int p = 0; p < 2; p++)
                ldm_x4(bf[p], bS + p * 16 * 80 + ks * 32);
            #pragma unroll
            for (int mt = 0; mt < 4; mt++)
                #pragma unroll
                for (int nt = 0; nt < 4; nt++)
                    mma16816(acc[mt][nt], af[mt], bf[nt >> 1][(nt & 1) * 2],
                             bf[nt >> 1][(nt & 1) * 2 + 1]);
        }
        __syncthreads();
        if (c + 2 < NC) { load_chunk(c + 2, st); CP_COMMIT(); }
    }

    // ---------------- epilogue ----------------
    int mrow = lane >> 2;           // 0..7
    int ncl  = (lane & 3) * 2;      // 0,2,4,6
    #pragma unroll
    for (int mt = 0; mt < 4; mt++) {
        #pragma unroll
        for (int half = 0; half < 2; half++) {
            int m = m0 + wm * 64 + mt * 16 + mrow + half * 8;
            #pragma unroll
            for (int nt = 0; nt < 4; nt++) {
                int n = n0 + wn * 32 + nt * 8 + ncl;
                float v0 = acc[mt][nt][half * 2 + 0] + bias[n];
                float v1 = acc[mt][nt][half * 2 + 1] + bias[n + 1];
                if (FLAGS == 1) {
                    int sel = n / C_;
                    int nn = n - sel * C_;
                    float* dst = (sel == 0) ? out0 : (sel == 1) ? out1 : out2;
                    int b_ = m >> 8, t = m & 255;
                    int h = nn >> 6, d0 = nn & 63;
                    float2* p = (float2*)(dst + (((size_t)(b_ * H_ + h) * T_ + t) * 64 + d0));
                    *p = make_float2(v0, v1);
                } else if (FLAGS == 2) {
                    v0 = fmaxf(v0, 0.0f); v1 = fmaxf(v1, 0.0f);
                    __nv_bfloat16 h0, l0, h1, l1;
                    split2(v0, h0, l0); split2(v1, h1, l1);
                    __nv_bfloat162 hp(h0, h1), lp(l0, l1);
                    __nv_bfloat16* rowp = acat_out + (size_t)m * KC2 + n;
                    *(uint32_t*)(rowp)            = *(uint32_t*)&hp;
                    *(uint32_t*)(rowp + 2 * FF_)  = *(uint32_t*)&hp;
                    *(uint32_t*)(rowp + FF_)      = *(uint32_t*)&lp;
                } else {
                    if (FLAGS & 4) {
                        const float2 rv = *(const float2*)(resid + (size_t)m * N + n);
                        v0 += rv.x; v1 += rv.y;
                    }
                    *(float2*)(out0 + (size_t)m * N + n) = make_float2(v0, v1);
                }
            }
        }
    }
}

// ---------------- Attention (fp32 SIMT; next round's target) ------------------
constexpr int ATTN_SMEM = (2 * 64 * 68 + 64 * 257) * 4;

__global__ void __launch_bounds__(256)
attn_kernel(const float* __restrict__ Kg, const float* __restrict__ Qg,
            const float* __restrict__ Vg, float* __restrict__ Og)
{
    extern __shared__ float smf[];
    float* Ks = smf;
    float* Qs = smf + 64 * 68;
    float* P  = smf + 2 * 64 * 68;

    int tt = blockIdx.x;
    int h  = blockIdx.y;
    int b  = blockIdx.z;
    int bh = b * H_ + h;
    const float* Kb = Kg + (size_t)bh * T_ * D_;
    const float* Qb = Qg + (size_t)bh * T_ * D_;
    const float* Vb = Vg + (size_t)bh * T_ * D_;

    int tid = threadIdx.x;
    int ty = tid >> 4, tx = tid & 15;

    for (int qd = tid; qd < 64 * 16; qd += 256) {
        int rr = qd >> 4, c4 = qd & 15;
        float4 v = *(const float4*)(Kb + (tt * 64 + rr) * 64 + c4 * 4);
        *(float4*)&Ks[rr * 68 + c4 * 4] = v;
    }

    const float scale = rsqrtf((float)C_);
    int nst = tt + 1;

    for (int st = 0; st < nst; st++) {
        __syncthreads();
        for (int qd = tid; qd < 64 * 16; qd += 256) {
            int rr = qd >> 4, c4 = qd & 15;
            *(float4*)&Qs[rr * 68 + c4 * 4] =
                *(const float4*)(Qb + (st * 64 + rr) * 64 + c4 * 4);
        }
        __syncthreads();
        float acc[4][4];
        #pragma unroll
        for (int i2 = 0; i2 < 4; i2++)
            #pragma unroll
            for (int j = 0; j < 4; j++) acc[i2][j] = 0.0f;
        #pragma unroll
        for (int d = 0; d < 64; d++) {
            float a[4], bb[4];
            #pragma unroll
            for (int i2 = 0; i2 < 4; i2++) a[i2] = Ks[(ty * 4 + i2) * 68 + d];
            #pragma unroll
            for (int j = 0; j < 4; j++) bb[j] = Qs[(tx * 4 + j) * 68 + d];
            #pragma unroll
            for (int i2 = 0; i2 < 4; i2++)
                #pragma unroll
                for (int j = 0; j < 4; j++)
                    acc[i2][j] += a[i2] * bb[j];
        }
        #pragma unroll
        for (int i2 = 0; i2 < 4; i2++) {
            int tg = tt * 64 + ty * 4 + i2;
            #pragma unroll
            for (int j = 0; j < 4; j++) {
                int sg = st * 64 + tx * 4 + j;
                P[(ty * 4 + i2) * 257 + st * 64 + tx * 4 + j] =
                    (sg <= tg) ? acc[i2][j] * scale : -CUDART_INF_F;
            }
        }
    }
    __syncthreads();

    int wid = tid >> 5, lane = tid & 31;
    int send = nst * 64;
    for (int rr = wid; rr < 64; rr += 8) {
        float* Pr = P + rr * 257;
        float mx = -CUDART_INF_F;
        for (int s = lane; s < send; s += 32) mx = fmaxf(mx, Pr[s]);
        #pragma unroll
        for (int o = 16; o; o >>= 1) mx = fmaxf(mx, __shfl_xor_sync(0xffffffffu, mx, o));
        float sum = 0.0f;
        for (int s = lane; s < send; s += 32) {
            float e = __expf(Pr[s] - mx);
            Pr[s] = e;
            sum += e;
        }
        #pragma unroll
        for (int o = 16; o; o >>= 1) sum += __shfl_xor_sync(0xffffffffu, sum, o);
        float inv = 1.0f / sum;
        for (int s = lane; s < send; s += 32) Pr[s] *= inv;
    }

    float oacc[4][4];
    #pragma unroll
    for (int i2 = 0; i2 < 4; i2++)
        #pragma unroll
        for (int j = 0; j < 4; j++) oacc[i2][j] = 0.0f;

    for (int st = 0; st < nst; st++) {
        __syncthreads();
        for (int qd = tid; qd < 64 * 16; qd += 256) {
            int rr = qd >> 4, c4 = qd & 15;
            *(float4*)&Qs[rr * 68 + c4 * 4] =
                *(const float4*)(Vb + (st * 64 + rr) * 64 + c4 * 4);
        }
        __syncthreads();
        for (int s = 0; s < 64; s++) {
            float a[4], bb[4];
            #pragma unroll
            for (int i2 = 0; i2 < 4; i2++) a[i2] = P[(ty * 4 + i2) * 257 + st * 64 + s];
            #pragma unroll
            for (int j = 0; j < 4; j++) bb[j] = Qs[s * 68 + tx * 4 + j];
            #pragma unroll
            for (int i2 = 0; i2 < 4; i2++)
                #pragma unroll
                for (int j = 0; j < 4; j++)
                    oacc[i2][j] += a[i2] * bb[j];
        }
    }

    #pragma unroll
    for (int i2 = 0; i2 < 4; i2++) {
        int t = tt * 64 + ty * 4 + i2;
        #pragma unroll
        for (int j = 0; j < 4; j++) {
            int col = h * 64 + tx * 4 + j;
            Og[((size_t)b * T_ + t) * C_ + col] = oacc[i2][j];
        }
    }
}

// ---------------- host orchestration -------------------------------------------
extern "C" void kernel_launch(void* const* d_in, const int* in_sizes, int n_in,
                              void* d_out, int out_size)
{
    const float* x     = (const float*)d_in[0];
    const float* ln1_g = (const float*)d_in[1];
    const float* ln1_b = (const float*)d_in[2];
    const float* Wk    = (const float*)d_in[3];
    const float* bk    = (const float*)d_in[4];
    const float* Wq    = (const float*)d_in[5];
    const float* bq    = (const float*)d_in[6];
    const float* Wv    = (const float*)d_in[7];
    const float* bv    = (const float*)d_in[8];
    const float* Wp    = (const float*)d_in[9];
    const float* bp    = (const float*)d_in[10];
    const float* ln2_g = (const float*)d_in[11];
    const float* ln2_b = (const float*)d_in[12];
    const float* W1    = (const float*)d_in[13];
    const float* b1    = (const float*)d_in[14];
    const float* W2    = (const float*)d_in[15];
    const float* b2    = (const float*)d_in[16];
    float* out = (float*)d_out;

    __nv_bfloat16 *acatA, *acat4, *bqkv, *bcp, *bc1, *bc2;
    float *biasqkv, *k, *q, *v, *att, *x1;
    cudaGetSymbolAddress((void**)&acatA,   g_acatA);
    cudaGetSymbolAddress((void**)&acat4,   g_acat4);
    cudaGetSymbolAddress((void**)&bqkv,    g_bqkv);
    cudaGetSymbolAddress((void**)&bcp,     g_bcp);
    cudaGetSymbolAddress((void**)&bc1,     g_bc1);
    cudaGetSymbolAddress((void**)&bc2,     g_bc2);
    cudaGetSymbolAddress((void**)&biasqkv, g_biasqkv);
    cudaGetSymbolAddress((void**)&k,   g_k);
    cudaGetSymbolAddress((void**)&q,   g_q);
    cudaGetSymbolAddress((void**)&v,   g_v);
    cudaGetSymbolAddress((void**)&att, g_att);
    cudaGetSymbolAddress((void**)&x1,  g_x1);

    cudaFuncSetAttribute(attn_kernel, cudaFuncAttributeMaxDynamicSharedMemorySize, ATTN_SMEM);

    // weight / bias conversions (deterministic)
    bias_concat_kernel<<<5, 256>>>(bk, bq, bv, biasqkv);
    build_bcat_qkv_kernel<<<(3 * C_ * C_ + 255) / 256, 256>>>(Wk, Wq, Wv, bqkv);
    build_bcat_kernel<<<(C_ * C_ + 255) / 256, 256>>>(Wp, bcp, C_, C_);
    build_bcat_kernel<<<(C_ * FF_ + 255) / 256, 256>>>(W1, bc1, C_, FF_);
    build_bcat_kernel<<<(FF_ * C_ + 255) / 256, 256>>>(W2, bc2, FF_, C_);

    // 1. LN1 -> split acat
    ln_split_kernel<<<M_, 128>>>(x, ln1_g, ln1_b, acatA);

    // 2. fused QKV projection (N = 1152)
    mma_gemm<1><<<dim3(9, M_ / 128), 256>>>(
        acatA, bqkv, biasqkv, nullptr, k, q, v, nullptr, KC1, 3 * C_);

    // 3. attention
    attn_kernel<<<dim3(T_ / 64, H_, B_), 256, ATTN_SMEM>>>(k, q, v, att);

    // 4. output projection + residual
    split_rows_kernel<<<(int)(((size_t)M_ * C_) / 256), 256>>>(att, acatA);
    mma_gemm<4><<<dim3(3, M_ / 128), 256>>>(
        acatA, bcp, bp, x, x1, nullptr, nullptr, nullptr, KC1, C_);

    // 5. LN2 -> split acat
    ln_split_kernel<<<M_, 128>>>(x1, ln2_g, ln2_b, acatA);

    // 6. FFN up + ReLU -> split acat4 directly
    mma_gemm<2><<<dim3(12, M_ / 128), 256>>>(
        acatA, bc1, b1, nullptr, nullptr, nullptr, nullptr, acat4, KC1, FF_);

    // 7. FFN down + residual -> d_out
    mma_gemm<4><<<dim3(3, M_ / 128), 256>>>(
        acat4, bc2, b2, x1, out, nullptr, nullptr, nullptr, KC2, C_);
}

// round 5
// speedup vs baseline: 3.2708x; 1.1827x over previous
#include <cuda_runtime.h>
#include <cuda_bf16.h>
#include <math_constants.h>
#include <cstdint>
#include <cstddef>

// Problem constants
constexpr int B_  = 128;
constexpr int T_  = 256;
constexpr int C_  = 384;
constexpr int H_  = 6;
constexpr int D_  = 64;
constexpr int FF_ = 1536;
constexpr int M_  = B_ * T_;     // 32768
constexpr int KC1 = 3 * C_;      // 1152
constexpr int KC2 = 3 * FF_;     // 4608
constexpr int BH_ = B_ * H_;     // 768

// ---------------- scratch ----------------
__device__ __nv_bfloat16 g_acatA[(size_t)M_ * KC1];
__device__ __nv_bfloat16 g_acat4[(size_t)M_ * KC2];
__device__ __nv_bfloat16 g_bqkv [(size_t)(3 * C_) * KC1];
__device__ __nv_bfloat16 g_bcp  [(size_t)C_  * KC1];
__device__ __nv_bfloat16 g_bc1  [(size_t)FF_ * KC1];
__device__ __nv_bfloat16 g_bc2  [(size_t)C_  * KC2];
__device__ float g_biasqkv[3 * C_];
__device__ __nv_bfloat16 g_kc[(size_t)BH_ * T_ * 192];   // K cat [hi|lo|hi] along d
__device__ __nv_bfloat16 g_qc[(size_t)BH_ * T_ * 192];   // Q cat [hi|hi|lo] along d
__device__ __nv_bfloat16 g_vt[(size_t)BH_ * 64 * 768];   // V^T cat [hi|hi|lo] along s
__device__ float g_x1 [M_ * C_];

// ---------------- helpers ----------------
__device__ __forceinline__ uint32_t smem_u32(const void* p) {
    uint32_t a;
    asm("{ .reg .u64 t; cvta.to.shared.u64 t, %1; cvt.u32.u64 %0, t; }" : "=r"(a) : "l"(p));
    return a;
}
__device__ __forceinline__ void cp16(uint32_t dst, const void* src) {
    asm volatile("cp.async.cg.shared.global [%0], [%1], 16;" :: "r"(dst), "l"(src));
}
#define CP_COMMIT() asm volatile("cp.async.commit_group;" ::: "memory")
#define CP_WAIT0()  asm volatile("cp.async.wait_group 0;"  ::: "memory")
#define CP_WAIT1()  asm volatile("cp.async.wait_group 1;"  ::: "memory")

__device__ __forceinline__ void ldm_x4(uint32_t* r, uint32_t addr) {
    asm volatile("ldmatrix.sync.aligned.m8n8.x4.shared.b16 {%0,%1,%2,%3}, [%4];"
        : "=r"(r[0]), "=r"(r[1]), "=r"(r[2]), "=r"(r[3]) : "r"(addr));
}
__device__ __forceinline__ void mma16816(float* c, const uint32_t* a, uint32_t b0, uint32_t b1) {
    asm volatile("mma.sync.aligned.m16n8k16.row.col.f32.bf16.bf16.f32 "
        "{%0,%1,%2,%3}, {%4,%5,%6,%7}, {%8,%9}, {%0,%1,%2,%3};"
        : "+f"(c[0]), "+f"(c[1]), "+f"(c[2]), "+f"(c[3])
        : "r"(a[0]), "r"(a[1]), "r"(a[2]), "r"(a[3]), "r"(b0), "r"(b1));
}
__device__ __forceinline__ void split2(float v, __nv_bfloat16& hi, __nv_bfloat16& lo) {
    hi = __float2bfloat16(v);
    lo = __float2bfloat16(v - __bfloat162float(hi));
}
__device__ __forceinline__ uint32_t pack2(__nv_bfloat16 a, __nv_bfloat16 b) {
    __nv_bfloat162 p(a, b);
    return *(uint32_t*)&p;
}

// ---------------- LayerNorm -> split activation cat [hi|lo|hi] ----------------
__global__ void ln_split_kernel(const float* __restrict__ x, const float* __restrict__ g,
                                const float* __restrict__ b, __nv_bfloat16* __restrict__ acat)
{
    int row = blockIdx.x;
    const float* xr = x + (size_t)row * C_;
    int tid = threadIdx.x;
    float v0 = xr[tid], v1 = xr[tid + 128], v2 = xr[tid + 256];
    float s  = v0 + v1 + v2;
    float sq = v0 * v0 + v1 * v1 + v2 * v2;
    #pragma unroll
    for (int o = 16; o; o >>= 1) {
        s  += __shfl_xor_sync(0xffffffffu, s,  o);
        sq += __shfl_xor_sync(0xffffffffu, sq, o);
    }
    __shared__ float red[2][4];
    int wid = tid >> 5, lane = tid & 31;
    if (lane == 0) { red[0][wid] = s; red[1][wid] = sq; }
    __syncthreads();
    s  = red[0][0] + red[0][1] + red[0][2] + red[0][3];
    sq = red[1][0] + red[1][1] + red[1][2] + red[1][3];
    float mu  = s * (1.0f / C_);
    float var = sq * (1.0f / C_) - mu * mu;
    float inv = rsqrtf(var + 1e-5f);
    __nv_bfloat16* orow = acat + (size_t)row * KC1;
    #pragma unroll
    for (int u = 0; u < 3; u++) {
        int k = tid + u * 128;
        float vv = (u == 0 ? v0 : (u == 1 ? v1 : v2));
        float y = (vv - mu) * inv * g[k] + b[k];
        __nv_bfloat16 hi, lo; split2(y, hi, lo);
        orow[k] = hi; orow[C_ + k] = lo; orow[2 * C_ + k] = hi;
    }
}

// ---------------- weight builders ----------------
__global__ void build_bcat_kernel(const float* __restrict__ W, __nv_bfloat16* __restrict__ Bcat,
                                  int K, int N)
{
    size_t idx = (size_t)blockIdx.x * 256 + threadIdx.x;
    if (idx >= (size_t)K * N) return;
    int n = (int)(idx / K);
    int k = (int)(idx % K);
    float v = W[(size_t)k * N + n];
    __nv_bfloat16 hi, lo; split2(v, hi, lo);
    size_t base = (size_t)n * 3 * K;
    Bcat[base + k] = hi; Bcat[base + K + k] = hi; Bcat[base + 2 * K + k] = lo;
}

__global__ void build_bcat_qkv_kernel(const float* __restrict__ Wk, const float* __restrict__ Wq,
                                      const float* __restrict__ Wv, __nv_bfloat16* __restrict__ Bcat)
{
    size_t idx = (size_t)blockIdx.x * 256 + threadIdx.x;
    if (idx >= (size_t)(3 * C_) * C_) return;
    int n = (int)(idx / C_);
    int k = (int)(idx % C_);
    int sel = n / C_;
    int nn = n - sel * C_;
    int h = nn >> 6, d = nn & 63;
    const float* Ws = (sel == 0) ? Wk : (sel == 1) ? Wq : Wv;
    float v = Ws[((size_t)h * C_ + k) * 64 + d];
    __nv_bfloat16 hi, lo; split2(v, hi, lo);
    size_t base = (size_t)n * KC1;
    Bcat[base + k] = hi; Bcat[base + C_ + k] = hi; Bcat[base + 2 * C_ + k] = lo;
}

__global__ void bias_concat_kernel(const float* __restrict__ bk, const float* __restrict__ bq,
                                   const float* __restrict__ bv, float* __restrict__ out)
{
    int t = blockIdx.x * 256 + threadIdx.x;
    if (t >= 3 * C_) return;
    int sel = t / C_, nn = t % C_;
    out[t] = (sel == 0 ? bk : sel == 1 ? bq : bv)[nn];
}

// ---------------- mma.sync GEMM: 128x128 tile, BK=32, 8 warps -----------------
// FLAGS: 1 = QKV cat store (out0/1/2 are bf16* kc/qc/vt), 2 = ReLU + split acat4,
//        4 = residual add, 0 = plain
template<int FLAGS>
__global__ void __launch_bounds__(256)
mma_gemm(const __nv_bfloat16* __restrict__ A, const __nv_bfloat16* __restrict__ Bc,
         const float* __restrict__ bias, const float* __restrict__ resid,
         float* __restrict__ out0, float* __restrict__ out1, float* __restrict__ out2,
         __nv_bfloat16* __restrict__ acat_out, int Kc, int N)
{
    __shared__ __align__(16) __nv_bfloat16 sA[2][128][40];
    __shared__ __align__(16) __nv_bfloat16 sB[2][128][40];

    int tid  = threadIdx.x;
    int wid  = tid >> 5;
    int lane = tid & 31;
    int wm = wid >> 2;
    int wn = wid & 3;
    int m0 = blockIdx.y * 128;
    int n0 = blockIdx.x * 128;
    int NC = Kc / 32;

    int lrow = tid >> 2;
    int lseg = tid & 3;
    const __nv_bfloat16* aRow0 = A  + (size_t)(m0 + lrow)      * Kc + lseg * 8;
    const __nv_bfloat16* aRow1 = A  + (size_t)(m0 + lrow + 64) * Kc + lseg * 8;
    const __nv_bfloat16* bRow0 = Bc + (size_t)(n0 + lrow)      * Kc + lseg * 8;
    const __nv_bfloat16* bRow1 = Bc + (size_t)(n0 + lrow + 64) * Kc + lseg * 8;

    uint32_t dA0 = smem_u32(&sA[0][lrow][lseg * 8]);
    uint32_t dA1 = smem_u32(&sA[0][lrow + 64][lseg * 8]);
    uint32_t dB0 = smem_u32(&sB[0][lrow][lseg * 8]);
    uint32_t dB1 = smem_u32(&sB[0][lrow + 64][lseg * 8]);
    constexpr uint32_t STG_A = sizeof(sA) / 2;
    constexpr uint32_t STG_B = sizeof(sB) / 2;

    auto load_chunk = [&](int c, int st) {
        size_t ko = (size_t)c * 32;
        uint32_t oa = st * STG_A, ob = st * STG_B;
        cp16(dA0 + oa, aRow0 + ko);
        cp16(dA1 + oa, aRow1 + ko);
        cp16(dB0 + ob, bRow0 + ko);
        cp16(dB1 + ob, bRow1 + ko);
    };

    int q = lane >> 3, i = lane & 7;
    uint32_t aAddr = smem_u32(&sA[0][wm * 64 + (q & 1) * 8 + i][(q >> 1) * 8]);
    uint32_t bAddr = smem_u32(&sB[0][wn * 32 + (q >> 1) * 8 + i][(q & 1) * 8]);

    float acc[4][4][4];
    #pragma unroll
    for (int mt = 0; mt < 4; mt++)
        #pragma unroll
        for (int nt = 0; nt < 4; nt++)
            #pragma unroll
            for (int r = 0; r < 4; r++) acc[mt][nt][r] = 0.0f;

    load_chunk(0, 0); CP_COMMIT();
    if (NC > 1) { load_chunk(1, 1); CP_COMMIT(); }

    for (int c = 0; c < NC; c++) {
        int st = c & 1;
        if (c + 1 < NC) CP_WAIT1(); else CP_WAIT0();
        __syncthreads();

        uint32_t aS = aAddr + st * STG_A;
        uint32_t bS = bAddr + st * STG_B;
        #pragma unroll
        for (int ks = 0; ks < 2; ks++) {
            uint32_t af[4][4], bf[2][4];
            #pragma unroll
            for (int mt = 0; mt < 4; mt++)
                ldm_x4(af[mt], aS + mt * 16 * 80 + ks * 32);
            #pragma unroll
            for (int p = 0; p < 2; p++)
                ldm_x4(bf[p], bS + p * 16 * 80 + ks * 32);
            #pragma unroll
            for (int mt = 0; mt < 4; mt++)
                #pragma unroll
                for (int nt = 0; nt < 4; nt++)
                    mma16816(acc[mt][nt], af[mt], bf[nt >> 1][(nt & 1) * 2],
                             bf[nt >> 1][(nt & 1) * 2 + 1]);
        }
        __syncthreads();
        if (c + 2 < NC) { load_chunk(c + 2, st); CP_COMMIT(); }
    }

    // ---------------- epilogue ----------------
    int mrow = lane >> 2;
    int ncl  = (lane & 3) * 2;
    #pragma unroll
    for (int mt = 0; mt < 4; mt++) {
        #pragma unroll
        for (int half = 0; half < 2; half++) {
            int m = m0 + wm * 64 + mt * 16 + mrow + half * 8;
            #pragma unroll
            for (int nt = 0; nt < 4; nt++) {
                int n = n0 + wn * 32 + nt * 8 + ncl;
                float v0 = acc[mt][nt][half * 2 + 0] + bias[n];
                float v1 = acc[mt][nt][half * 2 + 1] + bias[n + 1];
                if (FLAGS == 1) {
                    int sel = n / C_;
                    int nn = n - sel * C_;
                    int b_ = m >> 8, t = m & 255;
                    int hh = nn >> 6, d0 = nn & 63;
                    int bh = b_ * H_ + hh;
                    __nv_bfloat16 h0, l0, h1, l1;
                    split2(v0, h0, l0); split2(v1, h1, l1);
                    if (sel == 0) {                     // K cat [hi|lo|hi]
                        __nv_bfloat16* p = (__nv_bfloat16*)out0 +
                            ((size_t)bh * T_ + t) * 192 + d0;
                        *(uint32_t*)(p)       = pack2(h0, h1);
                        *(uint32_t*)(p + 64)  = pack2(l0, l1);
                        *(uint32_t*)(p + 128) = pack2(h0, h1);
                    } else if (sel == 1) {              // Q cat [hi|hi|lo]
                        __nv_bfloat16* p = (__nv_bfloat16*)out1 +
                            ((size_t)bh * T_ + t) * 192 + d0;
                        *(uint32_t*)(p)       = pack2(h0, h1);
                        *(uint32_t*)(p + 64)  = pack2(h0, h1);
                        *(uint32_t*)(p + 128) = pack2(l0, l1);
                    } else {                            // V^T cat [hi|hi|lo] along s
                        __nv_bfloat16* p0 = (__nv_bfloat16*)out2 +
                            ((size_t)bh * 64 + d0) * 768 + t;
                        p0[0] = h0; p0[256] = h0; p0[512] = l0;
                        __nv_bfloat16* p1 = p0 + 768;
                        p1[0] = h1; p1[256] = h1; p1[512] = l1;
                    }
                } else if (FLAGS == 2) {
                    v0 = fmaxf(v0, 0.0f); v1 = fmaxf(v1, 0.0f);
                    __nv_bfloat16 h0, l0, h1, l1;
                    split2(v0, h0, l0); split2(v1, h1, l1);
                    uint32_t hp = pack2(h0, h1), lp = pack2(l0, l1);
                    __nv_bfloat16* rowp = acat_out + (size_t)m * KC2 + n;
                    *(uint32_t*)(rowp)           = hp;
                    *(uint32_t*)(rowp + 2 * FF_) = hp;
                    *(uint32_t*)(rowp + FF_)     = lp;
                } else {
                    if (FLAGS & 4) {
                        const float2 rv = *(const float2*)(resid + (size_t)m * N + n);
                        v0 += rv.x; v1 += rv.y;
                    }
                    *(float2*)(out0 + (size_t)m * N + n) = make_float2(v0, v1);
                }
            }
        }
    }
}

// ---------------- flash attention with mma.sync (split-bf16) -------------------
// CTA: (t-tile 128) x head x batch. smem row stride 200 bf16 = 400B (16*25, odd
// multiple of 16B -> ldmatrix conflict-free).
constexpr int AST   = 200;
constexpr uint32_t OFF_K = 0;                       // 128 rows
constexpr uint32_t OFF_Q = 128u * AST * 2;          // 2 stages x 64 rows
constexpr uint32_t QSTG  = 64u * AST * 2;           // 25600
constexpr uint32_t OFF_V = OFF_Q + 2 * QSTG;
constexpr uint32_t OFF_P = OFF_V + 2 * QSTG;        // 128 rows
constexpr int ATTN2_SMEM = (int)(OFF_P + 128u * AST * 2);   // 204800

__global__ void __launch_bounds__(256)
attn_mma(const __nv_bfloat16* __restrict__ Kc, const __nv_bfloat16* __restrict__ Qc,
         const __nv_bfloat16* __restrict__ Vt, __nv_bfloat16* __restrict__ acat)
{
    extern __shared__ char smb[];
    uint32_t sb = smem_u32(smb);
    int tid = threadIdx.x, wid = tid >> 5, lane = tid & 31;
    int tt = blockIdx.x, h = blockIdx.y, b = blockIdx.z;
    int bh = b * H_ + h;
    const __nv_bfloat16* Kg = Kc + ((size_t)bh * T_ + (size_t)tt * 128) * 192;
    const __nv_bfloat16* Qg = Qc + (size_t)bh * T_ * 192;
    const __nv_bfloat16* Vg = Vt + (size_t)bh * 64 * 768;

    // K tile: 128 rows x 24 chunks of 16B
    #pragma unroll
    for (int it = 0; it < 12; it++) {
        int ch = tid + it * 256;
        int r = ch / 24, c = ch % 24;
        cp16(sb + OFF_K + r * 400 + c * 16, Kg + (size_t)r * 192 + c * 8);
    }
    CP_COMMIT();

    int nst = tt * 2 + 2;
    auto loadQV = [&](int st) {
        int stg = st & 1;
        const __nv_bfloat16* Qt = Qg + (size_t)st * 64 * 192;
        #pragma unroll
        for (int it = 0; it < 6; it++) {
            int ch = tid + it * 256;
            int r = ch / 24, c = ch % 24;
            cp16(sb + OFF_Q + stg * QSTG + r * 400 + c * 16, Qt + (size_t)r * 192 + c * 8);
        }
        #pragma unroll
        for (int it = 0; it < 6; it++) {
            int ch = tid + it * 256;
            int r = ch / 24, c = ch % 24;
            int seg = c >> 3, j = c & 7;
            int gcol = seg * 256 + st * 64 + j * 8;
            cp16(sb + OFF_V + stg * QSTG + r * 400 + c * 16, Vg + (size_t)r * 768 + gcol);
        }
        CP_COMMIT();
    };
    loadQV(0);

    float m_run[2] = { -CUDART_INF_F, -CUDART_INF_F };
    float l_run[2] = { 0.0f, 0.0f };
    float oacc[8][4];
    #pragma unroll
    for (int nt = 0; nt < 8; nt++)
        #pragma unroll
        for (int e = 0; e < 4; e++) oacc[nt][e] = 0.0f;

    const float scl = rsqrtf((float)C_);
    int q = lane >> 3, i5 = lane & 7;
    uint32_t aK = sb + OFF_K + (wid * 16 + (q & 1) * 8 + i5) * 400 + (q >> 1) * 16;
    uint32_t aP = sb + OFF_P + (wid * 16 + (q & 1) * 8 + i5) * 400 + (q >> 1) * 16;
    uint32_t bQ = sb + OFF_Q + ((q >> 1) * 8 + i5) * 400 + (q & 1) * 16;
    uint32_t bV = sb + OFF_V + ((q >> 1) * 8 + i5) * 400 + (q & 1) * 16;

    int r0 = lane >> 2;
    int tg0 = tt * 128 + wid * 16 + r0;
    int tg1 = tg0 + 8;
    __nv_bfloat16* sP = (__nv_bfloat16*)(smb + OFF_P);

    for (int st = 0; st < nst; st++) {
        int stg = st & 1;
        if (st + 1 < nst) { loadQV(st + 1); CP_WAIT1(); } else { CP_WAIT0(); }
        __syncthreads();

        // scores S = K . Q  (k' = 192 -> 12 k-steps)
        float sacc[8][4];
        #pragma unroll
        for (int nt = 0; nt < 8; nt++)
            #pragma unroll
            for (int e = 0; e < 4; e++) sacc[nt][e] = 0.0f;
        #pragma unroll
        for (int ks = 0; ks < 12; ks++) {
            uint32_t af[4], bf[4][4];
            ldm_x4(af, aK + ks * 32);
            #pragma unroll
            for (int p = 0; p < 4; p++)
                ldm_x4(bf[p], bQ + stg * QSTG + p * 16 * 400 + ks * 32);
            #pragma unroll
            for (int nt = 0; nt < 8; nt++)
                mma16816(sacc[nt], af, bf[nt >> 1][(nt & 1) * 2],
                         bf[nt >> 1][(nt & 1) * 2 + 1]);
        }

        // scale + causal mask + row max
        float mx0 = -CUDART_INF_F, mx1 = -CUDART_INF_F;
        #pragma unroll
        for (int nt = 0; nt < 8; nt++) {
            #pragma unroll
            for (int e = 0; e < 2; e++) {
                int sg = st * 64 + nt * 8 + (lane & 3) * 2 + e;
                float v0 = sacc[nt][e] * scl;
                if (sg > tg0) v0 = -CUDART_INF_F;
                sacc[nt][e] = v0; mx0 = fmaxf(mx0, v0);
                float v1 = sacc[nt][2 + e] * scl;
                if (sg > tg1) v1 = -CUDART_INF_F;
                sacc[nt][2 + e] = v1; mx1 = fmaxf(mx1, v1);
            }
        }
        mx0 = fmaxf(mx0, __shfl_xor_sync(0xffffffffu, mx0, 1));
        mx0 = fmaxf(mx0, __shfl_xor_sync(0xffffffffu, mx0, 2));
        mx1 = fmaxf(mx1, __shfl_xor_sync(0xffffffffu, mx1, 1));
        mx1 = fmaxf(mx1, __shfl_xor_sync(0xffffffffu, mx1, 2));

        float mn0 = fmaxf(m_run[0], mx0), mn1 = fmaxf(m_run[1], mx1);
        float es0 = __expf(m_run[0] - mn0), es1 = __expf(m_run[1] - mn1);
        m_run[0] = mn0; m_run[1] = mn1;

        float sum0 = 0.0f, sum1 = 0.0f;
        #pragma unroll
        for (int nt = 0; nt < 8; nt++) {
            #pragma unroll
            for (int e = 0; e < 2; e++) {
                float p0 = __expf(sacc[nt][e] - mn0);     sacc[nt][e] = p0;     sum0 += p0;
                float p1 = __expf(sacc[nt][2 + e] - mn1); sacc[nt][2 + e] = p1; sum1 += p1;
            }
        }
        sum0 += __shfl_xor_sync(0xffffffffu, sum0, 1);
        sum0 += __shfl_xor_sync(0xffffffffu, sum0, 2);
        sum1 += __shfl_xor_sync(0xffffffffu, sum1, 1);
        sum1 += __shfl_xor_sync(0xffffffffu, sum1, 2);
        l_run[0] = l_run[0] * es0 + sum0;
        l_run[1] = l_run[1] * es1 + sum1;

        // rescale O accumulator
        #pragma unroll
        for (int nt = 0; nt < 8; nt++) {
            oacc[nt][0] *= es0; oacc[nt][1] *= es0;
            oacc[nt][2] *= es1; oacc[nt][3] *= es1;
        }

        // write P cat [Phi|Plo|Phi] to smem
        #pragma unroll
        for (int nt = 0; nt < 8; nt++) {
            int cb = nt * 8 + (lane & 3) * 2;
            __nv_bfloat16 h0, l0, h1, l1;
            split2(sacc[nt][0], h0, l0); split2(sacc[nt][1], h1, l1);
            __nv_bfloat16* pr = sP + (wid * 16 + r0) * AST + cb;
            *(uint32_t*)(pr)       = pack2(h0, h1);
            *(uint32_t*)(pr + 64)  = pack2(l0, l1);
            *(uint32_t*)(pr + 128) = pack2(h0, h1);
            split2(sacc[nt][2], h0, l0); split2(sacc[nt][3], h1, l1);
            __nv_bfloat16* pr2 = pr + 8 * AST;
            *(uint32_t*)(pr2)       = pack2(h0, h1);
            *(uint32_t*)(pr2 + 64)  = pack2(l0, l1);
            *(uint32_t*)(pr2 + 128) = pack2(h0, h1);
        }
        __syncthreads();

        // O += P . V  (k' = 192)
        #pragma unroll
        for (int ks = 0; ks < 12; ks++) {
            uint32_t af[4], bf[4][4];
            ldm_x4(af, aP + ks * 32);
            #pragma unroll
            for (int p = 0; p < 4; p++)
                ldm_x4(bf[p], bV + stg * QSTG + p * 16 * 400 + ks * 32);
            #pragma unroll
            for (int nt = 0; nt < 8; nt++)
                mma16816(oacc[nt], af, bf[nt >> 1][(nt & 1) * 2],
                         bf[nt >> 1][(nt & 1) * 2 + 1]);
        }
        __syncthreads();
    }

    // epilogue: normalize, split, write acat rows directly (proj GEMM input)
    float inv0 = 1.0f / l_run[0], inv1 = 1.0f / l_run[1];
    int t0 = tt * 128 + wid * 16 + r0;
    size_t mrow0 = (size_t)(b * T_ + t0) * KC1;
    size_t mrow1 = mrow0 + (size_t)8 * KC1;
    #pragma unroll
    for (int nt = 0; nt < 8; nt++) {
        int k = h * 64 + nt * 8 + (lane & 3) * 2;
        {
            float v0 = oacc[nt][0] * inv0, v1 = oacc[nt][1] * inv0;
            __nv_bfloat16 h0, l0, h1, l1;
            split2(v0, h0, l0); split2(v1, h1, l1);
            __nv_bfloat16* p = g_acatA + mrow0 + k;
            *(uint32_t*)(p)          = pack2(h0, h1);
            *(uint32_t*)(p + C_)     = pack2(l0, l1);
            *(uint32_t*)(p + 2 * C_) = pack2(h0, h1);
        }
        {
            float v0 = oacc[nt][2] * inv1, v1 = oacc[nt][3] * inv1;
            __nv_bfloat16 h0, l0, h1, l1;
            split2(v0, h0, l0); split2(v1, h1, l1);
            __nv_bfloat16* p = g_acatA + mrow1 + k;
            *(uint32_t*)(p)          = pack2(h0, h1);
            *(uint32_t*)(p + C_)     = pack2(l0, l1);
            *(uint32_t*)(p + 2 * C_) = pack2(h0, h1);
        }
    }
}

// ---------------- host orchestration -------------------------------------------
extern "C" void kernel_launch(void* const* d_in, const int* in_sizes, int n_in,
                              void* d_out, int out_size)
{
    const float* x     = (const float*)d_in[0];
    const float* ln1_g = (const float*)d_in[1];
    const float* ln1_b = (const float*)d_in[2];
    const float* Wk    = (const float*)d_in[3];
    const float* bk    = (const float*)d_in[4];
    const float* Wq    = (const float*)d_in[5];
    const float* bq    = (const float*)d_in[6];
    const float* Wv    = (const float*)d_in[7];
    const float* bv    = (const float*)d_in[8];
    const float* Wp    = (const float*)d_in[9];
    const float* bp    = (const float*)d_in[10];
    const float* ln2_g = (const float*)d_in[11];
    const float* ln2_b = (const float*)d_in[12];
    const float* W1    = (const float*)d_in[13];
    const float* b1    = (const float*)d_in[14];
    const float* W2    = (const float*)d_in[15];
    const float* b2    = (const float*)d_in[16];
    float* out = (float*)d_out;

    __nv_bfloat16 *acatA, *acat4, *bqkv, *bcp, *bc1, *bc2, *kc, *qc, *vt;
    float *biasqkv, *x1;
    cudaGetSymbolAddress((void**)&acatA,   g_acatA);
    cudaGetSymbolAddress((void**)&acat4,   g_acat4);
    cudaGetSymbolAddress((void**)&bqkv,    g_bqkv);
    cudaGetSymbolAddress((void**)&bcp,     g_bcp);
    cudaGetSymbolAddress((void**)&bc1,     g_bc1);
    cudaGetSymbolAddress((void**)&bc2,     g_bc2);
    cudaGetSymbolAddress((void**)&biasqkv, g_biasqkv);
    cudaGetSymbolAddress((void**)&kc,  g_kc);
    cudaGetSymbolAddress((void**)&qc,  g_qc);
    cudaGetSymbolAddress((void**)&vt,  g_vt);
    cudaGetSymbolAddress((void**)&x1,  g_x1);

    cudaFuncSetAttribute(attn_mma, cudaFuncAttributeMaxDynamicSharedMemorySize, ATTN2_SMEM);

    // weight / bias conversions
    bias_concat_kernel<<<5, 256>>>(bk, bq, bv, biasqkv);
    build_bcat_qkv_kernel<<<(3 * C_ * C_ + 255) / 256, 256>>>(Wk, Wq, Wv, bqkv);
    build_bcat_kernel<<<(C_ * C_ + 255) / 256, 256>>>(Wp, bcp, C_, C_);
    build_bcat_kernel<<<(C_ * FF_ + 255) / 256, 256>>>(W1, bc1, C_, FF_);
    build_bcat_kernel<<<(FF_ * C_ + 255) / 256, 256>>>(W2, bc2, FF_, C_);

    // 1. LN1 -> split acat
    ln_split_kernel<<<M_, 128>>>(x, ln1_g, ln1_b, acatA);

    // 2. fused QKV projection -> Kcat/Qcat/V^Tcat bf16 directly
    mma_gemm<1><<<dim3(9, M_ / 128), 256>>>(
        acatA, bqkv, biasqkv, nullptr, (float*)kc, (float*)qc, (float*)vt,
        nullptr, KC1, 3 * C_);

    // 3. flash attention (writes proj input acatA directly)
    attn_mma<<<dim3(2, H_, B_), 256, ATTN2_SMEM>>>(kc, qc, vt, acatA);

    // 4. output projection + residual
    mma_gemm<4><<<dim3(3, M_ / 128), 256>>>(
        acatA, bcp, bp, x, x1, nullptr, nullptr, nullptr, KC1, C_);

    // 5. LN2 -> split acat
    ln_split_kernel<<<M_, 128>>>(x1, ln2_g, ln2_b, acatA);

    // 6. FFN up + ReLU -> split acat4 directly
    mma_gemm<2><<<dim3(12, M_ / 128), 256>>>(
        acatA, bc1, b1, nullptr, nullptr, nullptr, nullptr, acat4, KC1, FF_);

    // 7. FFN down + residual -> d_out
    mma_gemm<4><<<dim3(3, M_ / 128), 256>>>(
        acat4, bc2, b2, x1, out, nullptr, nullptr, nullptr, KC2, C_);
}

// round 7
// speedup vs baseline: 3.7775x; 1.1549x over previous
#include <cuda_runtime.h>
#include <cuda_bf16.h>
#include <math_constants.h>
#include <cstdint>
#include <cstddef>

// Problem constants
constexpr int B_  = 128;
constexpr int T_  = 256;
constexpr int C_  = 384;
constexpr int H_  = 6;
constexpr int D_  = 64;
constexpr int FF_ = 1536;
constexpr int M_  = B_ * T_;     // 32768
constexpr int KL1 = 3 * C_;      // 1152 logical K (3-term)
constexpr int KL2 = 3 * FF_;     // 4608
constexpr int KW1 = 2 * C_;      // 768  physical [hi|lo] width
constexpr int KW4 = 2 * FF_;     // 3072
constexpr int BH_ = B_ * H_;     // 768

// ---------------- scratch ----------------
__device__ __nv_bfloat16 g_acatA[(size_t)M_ * KW1];      // [hi|lo]
__device__ __nv_bfloat16 g_acat4[(size_t)M_ * KW4];      // [hi|lo]
__device__ __nv_bfloat16 g_bqkv [(size_t)(3 * C_) * KL1]; // weights keep [hi|hi|lo]
__device__ __nv_bfloat16 g_bcp  [(size_t)C_  * KL1];
__device__ __nv_bfloat16 g_bc1  [(size_t)FF_ * KL1];
__device__ __nv_bfloat16 g_bc2  [(size_t)C_  * KL2];
__device__ float g_biasqkv[3 * C_];
__device__ __nv_bfloat16 g_kc[(size_t)BH_ * T_ * 128];   // K [hi|lo] along d
__device__ __nv_bfloat16 g_qc[(size_t)BH_ * T_ * 128];   // Q [hi|lo] along d
__device__ __nv_bfloat16 g_vt[(size_t)BH_ * 64 * 512];   // V^T [hi|lo] along s
__device__ float g_x1 [M_ * C_];

// ---------------- helpers ----------------
__device__ __forceinline__ uint32_t smem_u32(const void* p) {
    uint32_t a;
    asm("{ .reg .u64 t; cvta.to.shared.u64 t, %1; cvt.u32.u64 %0, t; }" : "=r"(a) : "l"(p));
    return a;
}
__device__ __forceinline__ void cp16(uint32_t dst, const void* src) {
    asm volatile("cp.async.cg.shared.global [%0], [%1], 16;" :: "r"(dst), "l"(src));
}
#define CP_COMMIT() asm volatile("cp.async.commit_group;" ::: "memory")
#define CP_WAIT0()  asm volatile("cp.async.wait_group 0;"  ::: "memory")
#define CP_WAIT1()  asm volatile("cp.async.wait_group 1;"  ::: "memory")
#define CP_WAIT2()  asm volatile("cp.async.wait_group 2;"  ::: "memory")

__device__ __forceinline__ void ldm_x4(uint32_t* r, uint32_t addr) {
    asm volatile("ldmatrix.sync.aligned.m8n8.x4.shared.b16 {%0,%1,%2,%3}, [%4];"
        : "=r"(r[0]), "=r"(r[1]), "=r"(r[2]), "=r"(r[3]) : "r"(addr));
}
__device__ __forceinline__ void mma16816(float* c, const uint32_t* a, uint32_t b0, uint32_t b1) {
    asm volatile("mma.sync.aligned.m16n8k16.row.col.f32.bf16.bf16.f32 "
        "{%0,%1,%2,%3}, {%4,%5,%6,%7}, {%8,%9}, {%0,%1,%2,%3};"
        : "+f"(c[0]), "+f"(c[1]), "+f"(c[2]), "+f"(c[3])
        : "r"(a[0]), "r"(a[1]), "r"(a[2]), "r"(a[3]), "r"(b0), "r"(b1));
}
__device__ __forceinline__ void split2(float v, __nv_bfloat16& hi, __nv_bfloat16& lo) {
    hi = __float2bfloat16(v);
    lo = __float2bfloat16(v - __bfloat162float(hi));
}
__device__ __forceinline__ uint32_t pack2(__nv_bfloat16 a, __nv_bfloat16 b) {
    __nv_bfloat162 p(a, b);
    return *(uint32_t*)&p;
}

// ---------------- LayerNorm -> split activation [hi|lo] ----------------
__global__ void ln_split_kernel(const float* __restrict__ x, const float* __restrict__ g,
                                const float* __restrict__ b, __nv_bfloat16* __restrict__ acat)
{
    int row = blockIdx.x;
    const float* xr = x + (size_t)row * C_;
    int tid = threadIdx.x;
    float v0 = xr[tid], v1 = xr[tid + 128], v2 = xr[tid + 256];
    float s  = v0 + v1 + v2;
    float sq = v0 * v0 + v1 * v1 + v2 * v2;
    #pragma unroll
    for (int o = 16; o; o >>= 1) {
        s  += __shfl_xor_sync(0xffffffffu, s,  o);
        sq += __shfl_xor_sync(0xffffffffu, sq, o);
    }
    __shared__ float red[2][4];
    int wid = tid >> 5, lane = tid & 31;
    if (lane == 0) { red[0][wid] = s; red[1][wid] = sq; }
    __syncthreads();
    s  = red[0][0] + red[0][1] + red[0][2] + red[0][3];
    sq = red[1][0] + red[1][1] + red[1][2] + red[1][3];
    float mu  = s * (1.0f / C_);
    float var = sq * (1.0f / C_) - mu * mu;
    float inv = rsqrtf(var + 1e-5f);
    __nv_bfloat16* orow = acat + (size_t)row * KW1;
    #pragma unroll
    for (int u = 0; u < 3; u++) {
        int k = tid + u * 128;
        float vv = (u == 0 ? v0 : (u == 1 ? v1 : v2));
        float y = (vv - mu) * inv * g[k] + b[k];
        __nv_bfloat16 hi, lo; split2(y, hi, lo);
        orow[k] = hi; orow[C_ + k] = lo;
    }
}

// ---------------- weight builders (B keeps [hi|hi|lo], 3K wide) ---------------
__global__ void build_bcat_kernel(const float* __restrict__ W, __nv_bfloat16* __restrict__ Bcat,
                                  int K, int N)
{
    size_t idx = (size_t)blockIdx.x * 256 + threadIdx.x;
    if (idx >= (size_t)K * N) return;
    int n = (int)(idx / K);
    int k = (int)(idx % K);
    float v = W[(size_t)k * N + n];
    __nv_bfloat16 hi, lo; split2(v, hi, lo);
    size_t base = (size_t)n * 3 * K;
    Bcat[base + k] = hi; Bcat[base + K + k] = hi; Bcat[base + 2 * K + k] = lo;
}

__global__ void build_bcat_qkv_kernel(const float* __restrict__ Wk, const float* __restrict__ Wq,
                                      const float* __restrict__ Wv, __nv_bfloat16* __restrict__ Bcat)
{
    size_t idx = (size_t)blockIdx.x * 256 + threadIdx.x;
    if (idx >= (size_t)(3 * C_) * C_) return;
    int n = (int)(idx / C_);
    int k = (int)(idx % C_);
    int sel = n / C_;
    int nn = n - sel * C_;
    int h = nn >> 6, d = nn & 63;
    const float* Ws = (sel == 0) ? Wk : (sel == 1) ? Wq : Wv;
    float v = Ws[((size_t)h * C_ + k) * 64 + d];
    __nv_bfloat16 hi, lo; split2(v, hi, lo);
    size_t base = (size_t)n * KL1;
    Bcat[base + k] = hi; Bcat[base + C_ + k] = hi; Bcat[base + 2 * C_ + k] = lo;
}

__global__ void bias_concat_kernel(const float* __restrict__ bk, const float* __restrict__ bq,
                                   const float* __restrict__ bv, float* __restrict__ out)
{
    int t = blockIdx.x * 256 + threadIdx.x;
    if (t >= 3 * C_) return;
    int sel = t / C_, nn = t % C_;
    out[t] = (sel == 0 ? bk : sel == 1 ? bq : bv)[nn];
}

// ---------------- mma.sync GEMM: 128x128, BK=32, 4-stage async pipeline -------
// A physical [hi|lo] (width Aw = 2K0); logical K = 3K0 via chunk remap.
// FLAGS: 1 = QKV cat store, 2 = ReLU + [hi|lo] acat4, 4 = residual add, 0 = plain
constexpr uint32_t G_ASTG = 128u * 80;        // 10240 bytes per stage (one operand)
constexpr uint32_t G_BOFF = 4u * G_ASTG;      // B region offset
constexpr int GEMM_SMEM = (int)(8u * G_ASTG); // 81920

template<int FLAGS>
__global__ void __launch_bounds__(256)
mma_gemm(const __nv_bfloat16* __restrict__ A, const __nv_bfloat16* __restrict__ Bc,
         const float* __restrict__ bias, const float* __restrict__ resid,
         float* __restrict__ out0, float* __restrict__ out1, float* __restrict__ out2,
         __nv_bfloat16* __restrict__ acat_out, int Klog, int Aw, int N)
{
    extern __shared__ char gsm[];
    uint32_t sb = smem_u32(gsm);

    int tid  = threadIdx.x;
    int wid  = tid >> 5;
    int lane = tid & 31;
    int wm = wid >> 2;
    int wn = wid & 3;
    int m0 = blockIdx.y * 128;
    int n0 = blockIdx.x * 128;
    int NC  = Klog / 32;
    int KQ2 = (Klog / 96) * 2;     // chunks covering [hi|lo]

    int lrow = tid >> 2;
    int lseg = tid & 3;
    const __nv_bfloat16* aBase0 = A  + (size_t)(m0 + lrow)      * Aw + lseg * 8;
    const __nv_bfloat16* aBase1 = A  + (size_t)(m0 + lrow + 64) * Aw + lseg * 8;
    const __nv_bfloat16* bBase0 = Bc + (size_t)(n0 + lrow)      * Klog + lseg * 8;
    const __nv_bfloat16* bBase1 = Bc + (size_t)(n0 + lrow + 64) * Klog + lseg * 8;

    uint32_t dA0 = sb + lrow * 80 + lseg * 16;
    uint32_t dA1 = dA0 + 64 * 80;
    uint32_t dB0 = dA0 + G_BOFF;
    uint32_t dB1 = dA1 + G_BOFF;

    auto load_chunk = [&](int c, int st) {
        int pc = (c < KQ2) ? c : c - KQ2;
        uint32_t o = (uint32_t)st * G_ASTG;
        cp16(dA0 + o, aBase0 + (size_t)pc * 32);
        cp16(dA1 + o, aBase1 + (size_t)pc * 32);
        cp16(dB0 + o, bBase0 + (size_t)c * 32);
        cp16(dB1 + o, bBase1 + (size_t)c * 32);
    };

    int q = lane >> 3, i = lane & 7;
    uint32_t aOff = sb + (wm * 64 + (q & 1) * 8 + i) * 80 + (q >> 1) * 16;
    uint32_t bOff = sb + G_BOFF + (wn * 32 + (q >> 1) * 8 + i) * 80 + (q & 1) * 16;

    float acc[4][4][4];
    #pragma unroll
    for (int mt = 0; mt < 4; mt++)
        #pragma unroll
        for (int nt = 0; nt < 4; nt++)
            #pragma unroll
            for (int r = 0; r < 4; r++) acc[mt][nt][r] = 0.0f;

    #pragma unroll
    for (int s = 0; s < 3; s++) { load_chunk(s, s); CP_COMMIT(); }

    for (int c = 0; c < NC; c++) {
        int st = c & 3;
        CP_WAIT2();
        __syncthreads();
        if (c + 3 < NC) load_chunk(c + 3, (c + 3) & 3);
        CP_COMMIT();

        uint32_t aS = aOff + (uint32_t)st * G_ASTG;
        uint32_t bS = bOff + (uint32_t)st * G_ASTG;
        #pragma unroll
        for (int ks = 0; ks < 2; ks++) {
            uint32_t af[4][4], bf[2][4];
            #pragma unroll
            for (int mt = 0; mt < 4; mt++)
                ldm_x4(af[mt], aS + mt * 16 * 80 + ks * 32);
            #pragma unroll
            for (int p = 0; p < 2; p++)
                ldm_x4(bf[p], bS + p * 16 * 80 + ks * 32);
            #pragma unroll
            for (int mt = 0; mt < 4; mt++)
                #pragma unroll
                for (int nt = 0; nt < 4; nt++)
                    mma16816(acc[mt][nt], af[mt], bf[nt >> 1][(nt & 1) * 2],
                             bf[nt >> 1][(nt & 1) * 2 + 1]);
        }
    }

    // ---------------- epilogue ----------------
    int mrow = lane >> 2;
    int ncl  = (lane & 3) * 2;
    #pragma unroll
    for (int mt = 0; mt < 4; mt++) {
        #pragma unroll
        for (int half = 0; half < 2; half++) {
            int m = m0 + wm * 64 + mt * 16 + mrow + half * 8;
            #pragma unroll
            for (int nt = 0; nt < 4; nt++) {
                int n = n0 + wn * 32 + nt * 8 + ncl;
                float v0 = acc[mt][nt][half * 2 + 0] + bias[n];
                float v1 = acc[mt][nt][half * 2 + 1] + bias[n + 1];
                if (FLAGS == 1) {
                    int sel = n / C_;
                    int nn = n - sel * C_;
                    int b_ = m >> 8, t = m & 255;
                    int hh = nn >> 6, d0 = nn & 63;
                    int bh = b_ * H_ + hh;
                    __nv_bfloat16 h0, l0, h1, l1;
                    split2(v0, h0, l0); split2(v1, h1, l1);
                    if (sel == 0) {                     // K [hi|lo], width 128
                        __nv_bfloat16* p = (__nv_bfloat16*)out0 +
                            ((size_t)bh * T_ + t) * 128 + d0;
                        *(uint32_t*)(p)      = pack2(h0, h1);
                        *(uint32_t*)(p + 64) = pack2(l0, l1);
                    } else if (sel == 1) {              // Q [hi|lo], width 128
                        __nv_bfloat16* p = (__nv_bfloat16*)out1 +
                            ((size_t)bh * T_ + t) * 128 + d0;
                        *(uint32_t*)(p)      = pack2(h0, h1);
                        *(uint32_t*)(p + 64) = pack2(l0, l1);
                    } else {                            // V^T [hi|lo] along s, width 512
                        __nv_bfloat16* p0 = (__nv_bfloat16*)out2 +
                            ((size_t)bh * 64 + d0) * 512 + t;
                        p0[0] = h0; p0[256] = l0;
                        __nv_bfloat16* p1 = p0 + 512;
                        p1[0] = h1; p1[256] = l1;
                    }
                } else if (FLAGS == 2) {
                    v0 = fmaxf(v0, 0.0f); v1 = fmaxf(v1, 0.0f);
                    __nv_bfloat16 h0, l0, h1, l1;
                    split2(v0, h0, l0); split2(v1, h1, l1);
                    __nv_bfloat16* rowp = acat_out + (size_t)m * KW4 + n;
                    *(uint32_t*)(rowp)       = pack2(h0, h1);
                    *(uint32_t*)(rowp + FF_) = pack2(l0, l1);
                } else {
                    if (FLAGS & 4) {
                        const float2 rv = *(const float2*)(resid + (size_t)m * N + n);
                        v0 += rv.x; v1 += rv.y;
                    }
                    *(float2*)(out0 + (size_t)m * N + n) = make_float2(v0, v1);
                }
            }
        }
    }
}

// ---------------- flash attention with mma.sync (split-bf16) -------------------
constexpr int AST   = 200;
constexpr uint32_t OFF_K = 0;
constexpr uint32_t OFF_Q = 128u * AST * 2;
constexpr uint32_t QSTG  = 64u * AST * 2;
constexpr uint32_t OFF_V = OFF_Q + 2 * QSTG;
constexpr uint32_t OFF_P = OFF_V + 2 * QSTG;
constexpr int ATTN2_SMEM = (int)(OFF_P + 128u * AST * 2);   // 204800

__global__ void __launch_bounds__(256)
attn_mma(const __nv_bfloat16* __restrict__ Kc, const __nv_bfloat16* __restrict__ Qc,
         const __nv_bfloat16* __restrict__ Vt, __nv_bfloat16* __restrict__ acat)
{
    extern __shared__ char smb[];
    uint32_t sb = smem_u32(smb);
    int tid = threadIdx.x, wid = tid >> 5, lane = tid & 31;
    int tt = blockIdx.x, h = blockIdx.y, b = blockIdx.z;
    int bh = b * H_ + h;
    const __nv_bfloat16* Kg = Kc + ((size_t)bh * T_ + (size_t)tt * 128) * 128;
    const __nv_bfloat16* Qg = Qc + (size_t)bh * T_ * 128;
    const __nv_bfloat16* Vg = Vt + (size_t)bh * 64 * 512;

    // K tile: logical [hi|lo|hi] from phys [hi|lo]: chunk c -> phys (c<16 ? c : c-16)
    #pragma unroll
    for (int it = 0; it < 12; it++) {
        int ch = tid + it * 256;
        int r = ch / 24, c = ch % 24;
        int pc = (c < 16) ? c : c - 16;
        cp16(sb + OFF_K + r * 400 + c * 16, Kg + (size_t)r * 128 + pc * 8);
    }
    CP_COMMIT();

    int nst = tt * 2 + 2;
    auto loadQV = [&](int st) {
        int stg = st & 1;
        const __nv_bfloat16* Qt = Qg + (size_t)st * 64 * 128;
        #pragma unroll
        for (int it = 0; it < 6; it++) {
            int ch = tid + it * 256;
            int r = ch / 24, c = ch % 24;
            // Q logical [hi|hi|lo] -> phys [hi|lo]: c<8 ? c : c-8
            int pc = (c < 8) ? c : c - 8;
            cp16(sb + OFF_Q + stg * QSTG + r * 400 + c * 16, Qt + (size_t)r * 128 + pc * 8);
        }
        #pragma unroll
        for (int it = 0; it < 6; it++) {
            int ch = tid + it * 256;
            int r = ch / 24, c = ch % 24;
            int seg = c >> 3, j = c & 7;
            // V logical [hi|hi|lo] s-blocks -> phys [hi|lo]
            int gcol = ((seg == 2) ? 256 : 0) + st * 64 + j * 8;
            cp16(sb + OFF_V + stg * QSTG + r * 400 + c * 16, Vg + (size_t)r * 512 + gcol);
        }
        CP_COMMIT();
    };
    loadQV(0);

    float m_run[2] = { -CUDART_INF_F, -CUDART_INF_F };
    float l_run[2] = { 0.0f, 0.0f };
    float oacc[8][4];
    #pragma unroll
    for (int nt = 0; nt < 8; nt++)
        #pragma unroll
        for (int e = 0; e < 4; e++) oacc[nt][e] = 0.0f;

    const float scl = rsqrtf((float)C_);
    int q = lane >> 3, i5 = lane & 7;
    uint32_t aK = sb + OFF_K + (wid * 16 + (q & 1) * 8 + i5) * 400 + (q >> 1) * 16;
    uint32_t aP = sb + OFF_P + (wid * 16 + (q & 1) * 8 + i5) * 400 + (q >> 1) * 16;
    uint32_t bQ = sb + OFF_Q + ((q >> 1) * 8 + i5) * 400 + (q & 1) * 16;
    uint32_t bV = sb + OFF_V + ((q >> 1) * 8 + i5) * 400 + (q & 1) * 16;

    int r0 = lane >> 2;
    int tg0 = tt * 128 + wid * 16 + r0;
    int tg1 = tg0 + 8;
    __nv_bfloat16* sP = (__nv_bfloat16*)(smb + OFF_P);

    for (int st = 0; st < nst; st++) {
        int stg = st & 1;
        if (st + 1 < nst) { loadQV(st + 1); CP_WAIT1(); } else { CP_WAIT0(); }
        __syncthreads();

        float sacc[8][4];
        #pragma unroll
        for (int nt = 0; nt < 8; nt++)
            #pragma unroll
            for (int e = 0; e < 4; e++) sacc[nt][e] = 0.0f;
        #pragma unroll
        for (int ks = 0; ks < 12; ks++) {
            uint32_t af[4], bf[4][4];
            ldm_x4(af, aK + ks * 32);
            #pragma unroll
            for (int p = 0; p < 4; p++)
                ldm_x4(bf[p], bQ + stg * QSTG + p * 16 * 400 + ks * 32);
            #pragma unroll
            for (int nt = 0; nt < 8; nt++)
                mma16816(sacc[nt], af, bf[nt >> 1][(nt & 1) * 2],
                         bf[nt >> 1][(nt & 1) * 2 + 1]);
        }

        float mx0 = -CUDART_INF_F, mx1 = -CUDART_INF_F;
        #pragma unroll
        for (int nt = 0; nt < 8; nt++) {
            #pragma unroll
            for (int e = 0; e < 2; e++) {
                int sg = st * 64 + nt * 8 + (lane & 3) * 2 + e;
                float v0 = sacc[nt][e] * scl;
                if (sg > tg0) v0 = -CUDART_INF_F;
                sacc[nt][e] = v0; mx0 = fmaxf(mx0, v0);
                float v1 = sacc[nt][2 + e] * scl;
                if (sg > tg1) v1 = -CUDART_INF_F;
                sacc[nt][2 + e] = v1; mx1 = fmaxf(mx1, v1);
            }
        }
        mx0 = fmaxf(mx0, __shfl_xor_sync(0xffffffffu, mx0, 1));
        mx0 = fmaxf(mx0, __shfl_xor_sync(0xffffffffu, mx0, 2));
        mx1 = fmaxf(mx1, __shfl_xor_sync(0xffffffffu, mx1, 1));
        mx1 = fmaxf(mx1, __shfl_xor_sync(0xffffffffu, mx1, 2));

        float mn0 = fmaxf(m_run[0], mx0), mn1 = fmaxf(m_run[1], mx1);
        float es0 = __expf(m_run[0] - mn0), es1 = __expf(m_run[1] - mn1);
        m_run[0] = mn0; m_run[1] = mn1;

        float sum0 = 0.0f, sum1 = 0.0f;
        #pragma unroll
        for (int nt = 0; nt < 8; nt++) {
            #pragma unroll
            for (int e = 0; e < 2; e++) {
                float p0 = __expf(sacc[nt][e] - mn0);     sacc[nt][e] = p0;     sum0 += p0;
                float p1 = __expf(sacc[nt][2 + e] - mn1); sacc[nt][2 + e] = p1; sum1 += p1;
            }
        }
        sum0 += __shfl_xor_sync(0xffffffffu, sum0, 1);
        sum0 += __shfl_xor_sync(0xffffffffu, sum0, 2);
        sum1 += __shfl_xor_sync(0xffffffffu, sum1, 1);
        sum1 += __shfl_xor_sync(0xffffffffu, sum1, 2);
        l_run[0] = l_run[0] * es0 + sum0;
        l_run[1] = l_run[1] * es1 + sum1;

        #pragma unroll
        for (int nt = 0; nt < 8; nt++) {
            oacc[nt][0] *= es0; oacc[nt][1] *= es0;
            oacc[nt][2] *= es1; oacc[nt][3] *= es1;
        }

        // P cat [Phi|Plo|Phi] in smem (smem is cheap; keep 3-wide for the PV mma)
        #pragma unroll
        for (int nt = 0; nt < 8; nt++) {
            int cb = nt * 8 + (lane & 3) * 2;
            __nv_bfloat16 h0, l0, h1, l1;
            split2(sacc[nt][0], h0, l0); split2(sacc[nt][1], h1, l1);
            __nv_bfloat16* pr = sP + (wid * 16 + r0) * AST + cb;
            *(uint32_t*)(pr)       = pack2(h0, h1);
            *(uint32_t*)(pr + 64)  = pack2(l0, l1);
            *(uint32_t*)(pr + 128) = pack2(h0, h1);
            split2(sacc[nt][2], h0, l0); split2(sacc[nt][3], h1, l1);
            __nv_bfloat16* pr2 = pr + 8 * AST;
            *(uint32_t*)(pr2)       = pack2(h0, h1);
            *(uint32_t*)(pr2 + 64)  = pack2(l0, l1);
            *(uint32_t*)(pr2 + 128) = pack2(h0, h1);
        }
        __syncthreads();

        #pragma unroll
        for (int ks = 0; ks < 12; ks++) {
            uint32_t af[4], bf[4][4];
            ldm_x4(af, aP + ks * 32);
            #pragma unroll
            for (int p = 0; p < 4; p++)
                ldm_x4(bf[p], bV + stg * QSTG + p * 16 * 400 + ks * 32);
            #pragma unroll
            for (int nt = 0; nt < 8; nt++)
                mma16816(oacc[nt], af, bf[nt >> 1][(nt & 1) * 2],
                         bf[nt >> 1][(nt & 1) * 2 + 1]);
        }
        __syncthreads();
    }

    // epilogue: normalize, split, write acatA [hi|lo] rows directly
    float inv0 = 1.0f / l_run[0], inv1 = 1.0f / l_run[1];
    int t0 = tt * 128 + wid * 16 + r0;
    size_t mrow0 = (size_t)(b * T_ + t0) * KW1;
    size_t mrow1 = mrow0 + (size_t)8 * KW1;
    #pragma unroll
    for (int nt = 0; nt < 8; nt++) {
        int k = h * 64 + nt * 8 + (lane & 3) * 2;
        {
            float v0 = oacc[nt][0] * inv0, v1 = oacc[nt][1] * inv0;
            __nv_bfloat16 h0, l0, h1, l1;
            split2(v0, h0, l0); split2(v1, h1, l1);
            __nv_bfloat16* p = g_acatA + mrow0 + k;
            *(uint32_t*)(p)      = pack2(h0, h1);
            *(uint32_t*)(p + C_) = pack2(l0, l1);
        }
        {
            float v0 = oacc[nt][2] * inv1, v1 = oacc[nt][3] * inv1;
            __nv_bfloat16 h0, l0, h1, l1;
            split2(v0, h0, l0); split2(v1, h1, l1);
            __nv_bfloat16* p = g_acatA + mrow1 + k;
            *(uint32_t*)(p)      = pack2(h0, h1);
            *(uint32_t*)(p + C_) = pack2(l0, l1);
        }
    }
}

// ---------------- host orchestration -------------------------------------------
extern "C" void kernel_launch(void* const* d_in, const int* in_sizes, int n_in,
                              void* d_out, int out_size)
{
    const float* x     = (const float*)d_in[0];
    const float* ln1_g = (const float*)d_in[1];
    const float* ln1_b = (const float*)d_in[2];
    const float* Wk    = (const float*)d_in[3];
    const float* bk    = (const float*)d_in[4];
    const float* Wq    = (const float*)d_in[5];
    const float* bq    = (const float*)d_in[6];
    const float* Wv    = (const float*)d_in[7];
    const float* bv    = (const float*)d_in[8];
    const float* Wp    = (const float*)d_in[9];
    const float* bp    = (const float*)d_in[10];
    const float* ln2_g = (const float*)d_in[11];
    const float* ln2_b = (const float*)d_in[12];
    const float* W1    = (const float*)d_in[13];
    const float* b1    = (const float*)d_in[14];
    const float* W2    = (const float*)d_in[15];
    const float* b2    = (const float*)d_in[16];
    float* out = (float*)d_out;

    __nv_bfloat16 *acatA, *acat4, *bqkv, *bcp, *bc1, *bc2, *kc, *qc, *vt;
    float *biasqkv, *x1;
    cudaGetSymbolAddress((void**)&acatA,   g_acatA);
    cudaGetSymbolAddress((void**)&acat4,   g_acat4);
    cudaGetSymbolAddress((void**)&bqkv,    g_bqkv);
    cudaGetSymbolAddress((void**)&bcp,     g_bcp);
    cudaGetSymbolAddress((void**)&bc1,     g_bc1);
    cudaGetSymbolAddress((void**)&bc2,     g_bc2);
    cudaGetSymbolAddress((void**)&biasqkv, g_biasqkv);
    cudaGetSymbolAddress((void**)&kc,  g_kc);
    cudaGetSymbolAddress((void**)&qc,  g_qc);
    cudaGetSymbolAddress((void**)&vt,  g_vt);
    cudaGetSymbolAddress((void**)&x1,  g_x1);

    cudaFuncSetAttribute(attn_mma, cudaFuncAttributeMaxDynamicSharedMemorySize, ATTN2_SMEM);
    cudaFuncSetAttribute(mma_gemm<1>, cudaFuncAttributeMaxDynamicSharedMemorySize, GEMM_SMEM);
    cudaFuncSetAttribute(mma_gemm<2>, cudaFuncAttributeMaxDynamicSharedMemorySize, GEMM_SMEM);
    cudaFuncSetAttribute(mma_gemm<4>, cudaFuncAttributeMaxDynamicSharedMemorySize, GEMM_SMEM);

    // weight / bias conversions
    bias_concat_kernel<<<5, 256>>>(bk, bq, bv, biasqkv);
    build_bcat_qkv_kernel<<<(3 * C_ * C_ + 255) / 256, 256>>>(Wk, Wq, Wv, bqkv);
    build_bcat_kernel<<<(C_ * C_ + 255) / 256, 256>>>(Wp, bcp, C_, C_);
    build_bcat_kernel<<<(C_ * FF_ + 255) / 256, 256>>>(W1, bc1, C_, FF_);
    build_bcat_kernel<<<(FF_ * C_ + 255) / 256, 256>>>(W2, bc2, FF_, C_);

    // 1. LN1 -> split acatA [hi|lo]
    ln_split_kernel<<<M_, 128>>>(x, ln1_g, ln1_b, acatA);

    // 2. fused QKV projection -> K/Q/V^T [hi|lo] bf16 directly
    mma_gemm<1><<<dim3(9, M_ / 128), 256, GEMM_SMEM>>>(
        acatA, bqkv, biasqkv, nullptr, (float*)kc, (float*)qc, (float*)vt,
        nullptr, KL1, KW1, 3 * C_);

    // 3. flash attention (writes proj input acatA directly)
    attn_mma<<<dim3(2, H_, B_), 256, ATTN2_SMEM>>>(kc, qc, vt, acatA);

    // 4. output projection + residual
    mma_gemm<4><<<dim3(3, M_ / 128), 256, GEMM_SMEM>>>(
        acatA, bcp, bp, x, x1, nullptr, nullptr, nullptr, KL1, KW1, C_);

    // 5. LN2 -> split acatA
    ln_split_kernel<<<M_, 128>>>(x1, ln2_g, ln2_b, acatA);

    // 6. FFN up + ReLU -> acat4 [hi|lo] directly
    mma_gemm<2><<<dim3(12, M_ / 128), 256, GEMM_SMEM>>>(
        acatA, bc1, b1, nullptr, nullptr, nullptr, nullptr, acat4, KL1, KW1, FF_);

    // 7. FFN down + residual -> d_out
    mma_gemm<4><<<dim3(3, M_ / 128), 256, GEMM_SMEM>>>(
        acat4, bc2, b2, x1, out, nullptr, nullptr, nullptr, KL2, KW4, C_);
}